// round 15
// baseline (speedup 1.0000x reference)
#include <cuda_runtime.h>
#include <cuda_bf16.h>
#include <cstdint>

#define B_SZ 8192
#define HID  1024
#define PROJ 512
#define KSEL 4096

// ======================= helpers =============================================
__device__ __forceinline__ uint32_t smem_to_u32(const void* p) {
    uint32_t a;
    asm("{ .reg .u64 t; cvta.to.shared.u64 t, %1; cvt.u32.u64 %0, t; }"
        : "=r"(a) : "l"(p));
    return a;
}
#define SW128(off) ((off) ^ (((off) >> 3) & 0x70))

__device__ __forceinline__ void cp_async16(uint32_t dst, const void* src) {
    asm volatile("cp.async.cg.shared.global [%0], [%1], 16;"
                 :: "r"(dst), "l"(src) : "memory");
}
__device__ __forceinline__ void ldsm_x4(uint32_t& r0, uint32_t& r1,
                                        uint32_t& r2, uint32_t& r3, uint32_t addr) {
    asm volatile("ldmatrix.sync.aligned.m8n8.x4.shared.b16 {%0,%1,%2,%3}, [%4];"
                 : "=r"(r0), "=r"(r1), "=r"(r2), "=r"(r3) : "r"(addr));
}
__device__ __forceinline__ void mma_bf16(float* c, const uint32_t* a,
                                         uint32_t b0, uint32_t b1) {
    asm volatile(
        "mma.sync.aligned.m16n8k16.row.col.f32.bf16.bf16.f32 "
        "{%0,%1,%2,%3}, {%4,%5,%6,%7}, {%8,%9}, {%0,%1,%2,%3};"
        : "+f"(c[0]), "+f"(c[1]), "+f"(c[2]), "+f"(c[3])
        : "r"(a[0]), "r"(a[1]), "r"(a[2]), "r"(a[3]), "r"(b0), "r"(b1));
}
__device__ __forceinline__ uint32_t bf2_pack(float a, float b) {
    __nv_bfloat162 h = __floats2bfloat162_rn(a, b);
    return *reinterpret_cast<uint32_t*>(&h);
}

// ======================= scratch (device globals) ============================
__device__ __align__(16) __nv_bfloat16 g_Wa_t[HID * 768];
__device__ __align__(16) __nv_bfloat16 g_Wa_v[HID * 2048];
__device__ __align__(16) __nv_bfloat16 g_W1_t[HID * HID];
__device__ __align__(16) __nv_bfloat16 g_W1_v[HID * HID];
__device__ __align__(16) __nv_bfloat16 g_W2_t[PROJ * HID];
__device__ __align__(16) __nv_bfloat16 g_W2_v[PROJ * HID];
__device__ __align__(16) __nv_bfloat16 g_cat [2 * B_SZ * HID];
__device__ __align__(16) __nv_bfloat16 g_hcat[2 * B_SZ * HID];
__device__ __align__(16) float         g_pcat[2 * B_SZ * PROJ];
__device__ __align__(16) __nv_bfloat16 g_mproj[2 * B_SZ * PROJ];
__device__ __align__(16) __nv_bfloat16 g_iproj[2 * B_SZ * PROJ];
__device__ float g_sim[2 * (size_t)B_SZ * B_SZ];
__device__ float g_ce[2 * B_SZ];

// ======================= HMMA GEMM (128x128 CTA tile, 2 stages) ==============
static constexpr int STAGES   = 2;
static constexpr int TC_DSMEM = STAGES * 32 * 1024 + 1024;
static constexpr int EPI_RS   = 132;

// A_FP32: A is fp32 in gmem; loader converts to bf16 on the fly (rn).
template <bool RELU, bool BIAS, bool OUT_BF16, bool ZBATCH, bool A_FP32>
__global__ __launch_bounds__(256, 2)
void hmma_gemm(const __nv_bfloat16* __restrict__ A, const __nv_bfloat16* __restrict__ Bw,
               const float* __restrict__ bias, void* __restrict__ Cout,
               int M, int N, int K, float scale)
{
    extern __shared__ char dsm[];
    const uint32_t base_u  = smem_to_u32(dsm);
    const uint32_t tiles_u = (base_u + 1023u) & ~1023u;
    char* tiles_p = dsm + (tiles_u - base_u);

    if (ZBATCH) {
        const size_t zo = (size_t)blockIdx.z;
        A    += zo * B_SZ * PROJ;
        Bw   += zo * B_SZ * PROJ;
        Cout  = (float*)Cout + zo * (size_t)B_SZ * B_SZ;
    }

    const int tid  = threadIdx.x;
    const int wid  = tid >> 5, lane = tid & 31;
    const int wm   = wid >> 2, wn = wid & 3;
    const int bm   = blockIdx.y * 128, bn = blockIdx.x * 128;
    const int nsteps = K >> 6;

    float acc[4][4][4];
#pragma unroll
    for (int i = 0; i < 4; i++)
#pragma unroll
        for (int j = 0; j < 4; j++)
#pragma unroll
            for (int r = 0; r < 4; r++) acc[i][j][r] = 0.f;

    const int lr = tid >> 3;
    const int lc = tid & 7;

    auto load_stage = [&](int buf, int k0) {
        const uint32_t tA = tiles_u + (uint32_t)buf * 32768u;
        const uint32_t tB = tA + 16384u;
#pragma unroll
        for (int h = 0; h < 4; h++) {
            int r = lr + h * 32;
            uint32_t sw = SW128((uint32_t)(r * 128 + lc * 16));
            if (A_FP32) {
                const float* Af = (const float*)A + (size_t)(bm + r) * K + k0 + lc * 8;
                float4 w0 = *(const float4*)Af;
                float4 w1 = *(const float4*)(Af + 4);
                uint4 v;
                v.x = bf2_pack(w0.x, w0.y);
                v.y = bf2_pack(w0.z, w0.w);
                v.z = bf2_pack(w1.x, w1.y);
                v.w = bf2_pack(w1.z, w1.w);
                *(uint4*)(tiles_p + (uint32_t)buf * 32768u + sw) = v;
            } else {
                cp_async16(tA + sw, A + (size_t)(bm + r) * K + k0 + lc * 8);
            }
            cp_async16(tB + sw, Bw + (size_t)(bn + r) * K + k0 + lc * 8);
        }
        asm volatile("cp.async.commit_group;" ::: "memory");
    };

    const int a_row  = wm * 64 + (lane & 15);
    const int a_colb = (lane >> 4) << 4;
    const int b_row0 = wn * 32 + (lane & 7) + ((lane >> 4) << 3);
    const int b_colb = ((lane >> 3) & 1) << 4;

    auto ld_frags = [&](uint32_t tA, uint32_t tB, int kk,
                        uint32_t a[4][4], uint32_t bf[2][4]) {
        const int kb = kk * 32;
#pragma unroll
        for (int mt = 0; mt < 4; ++mt)
            ldsm_x4(a[mt][0], a[mt][1], a[mt][2], a[mt][3],
                    tA + SW128((uint32_t)((a_row + mt * 16) * 128 + kb + a_colb)));
#pragma unroll
        for (int np = 0; np < 2; ++np)
            ldsm_x4(bf[np][0], bf[np][1], bf[np][2], bf[np][3],
                    tB + SW128((uint32_t)((b_row0 + np * 16) * 128 + kb + b_colb)));
    };

    load_stage(0, 0);

    uint32_t afr[2][4][4], bfr[2][2][4];

    for (int s = 0; s < nsteps; ++s) {
        if (s + 1 < nsteps) {
            load_stage((s + 1) & 1, (s + 1) << 6);
            asm volatile("cp.async.wait_group 1;" ::: "memory");
        } else {
            asm volatile("cp.async.wait_group 0;" ::: "memory");
        }
        __syncthreads();

        const uint32_t tA = tiles_u + (uint32_t)(s & 1) * 32768u;
        const uint32_t tB = tA + 16384u;

        ld_frags(tA, tB, 0, afr[0], bfr[0]);
#pragma unroll
        for (int kk = 0; kk < 4; ++kk) {
            const int cur = kk & 1;
            if (kk < 3) ld_frags(tA, tB, kk + 1, afr[cur ^ 1], bfr[cur ^ 1]);
#pragma unroll
            for (int mt = 0; mt < 4; ++mt)
#pragma unroll
                for (int nt = 0; nt < 4; ++nt)
                    mma_bf16(acc[mt][nt], afr[cur][mt],
                             bfr[cur][nt >> 1][(nt & 1) * 2],
                             bfr[cur][nt >> 1][(nt & 1) * 2 + 1]);
        }
        __syncthreads();
    }

    const int g = lane >> 2, tg = lane & 3;

    if (!OUT_BF16) {
        float* stage = (float*)tiles_p;
#pragma unroll
        for (int half = 0; half < 2; ++half) {
            if (wm == half) {
#pragma unroll
                for (int mt = 0; mt < 4; ++mt) {
#pragma unroll
                    for (int nt = 0; nt < 4; ++nt) {
                        const int r = mt * 16 + g;
                        const int c = wn * 32 + nt * 8 + tg * 2;
                        float v0 = acc[mt][nt][0], v1 = acc[mt][nt][1];
                        float v2 = acc[mt][nt][2], v3 = acc[mt][nt][3];
                        if (BIAS) {
                            float bb0 = bias[bn + c], bb1 = bias[bn + c + 1];
                            v0 += bb0; v1 += bb1; v2 += bb0; v3 += bb1;
                        }
                        v0 *= scale; v1 *= scale; v2 *= scale; v3 *= scale;
                        if (RELU) {
                            v0 = fmaxf(v0, 0.f); v1 = fmaxf(v1, 0.f);
                            v2 = fmaxf(v2, 0.f); v3 = fmaxf(v3, 0.f);
                        }
                        stage[r * EPI_RS + c]           = v0;
                        stage[r * EPI_RS + c + 1]       = v1;
                        stage[(r + 8) * EPI_RS + c]     = v2;
                        stage[(r + 8) * EPI_RS + c + 1] = v3;
                    }
                }
            }
            __syncthreads();
            float* C = (float*)Cout;
#pragma unroll
            for (int i = tid; i < 64 * 32; i += 256) {
                const int r  = i >> 5;
                const int c4 = i & 31;
                float4 v = *(float4*)&stage[r * EPI_RS + c4 * 4];
                *(float4*)(C + (size_t)(bm + half * 64 + r) * N + bn + c4 * 4) = v;
            }
            __syncthreads();
        }
    } else {
#pragma unroll
        for (int mt = 0; mt < 4; ++mt) {
#pragma unroll
            for (int nt = 0; nt < 4; ++nt) {
                const int m0 = bm + wm * 64 + mt * 16 + g;
                const int n0 = bn + wn * 32 + nt * 8 + tg * 2;
                float v0 = acc[mt][nt][0], v1 = acc[mt][nt][1];
                float v2 = acc[mt][nt][2], v3 = acc[mt][nt][3];
                if (BIAS) {
                    float bb0 = bias[n0], bb1 = bias[n0 + 1];
                    v0 += bb0; v1 += bb1; v2 += bb0; v3 += bb1;
                }
                v0 *= scale; v1 *= scale; v2 *= scale; v3 *= scale;
                if (RELU) {
                    v0 = fmaxf(v0, 0.f); v1 = fmaxf(v1, 0.f);
                    v2 = fmaxf(v2, 0.f); v3 = fmaxf(v3, 0.f);
                }
                __nv_bfloat16* C = (__nv_bfloat16*)Cout;
                *(__nv_bfloat162*)(C + (size_t)m0 * N + n0)       = __floats2bfloat162_rn(v0, v1);
                *(__nv_bfloat162*)(C + (size_t)(m0 + 8) * N + n0) = __floats2bfloat162_rn(v2, v3);
            }
        }
    }
}

// ======================= conversion / transpose ==============================
__global__ void cvt_bf16_kernel(const float* __restrict__ in,
                                __nv_bfloat16* __restrict__ out, int n4)
{
    int i = blockIdx.x * blockDim.x + threadIdx.x;
    if (i < n4) {
        float4 v = *(const float4*)(in + i * 4);
        __nv_bfloat162* o = (__nv_bfloat162*)(out + i * 4);
        o[0] = __floats2bfloat162_rn(v.x, v.y);
        o[1] = __floats2bfloat162_rn(v.z, v.w);
    }
}

struct TransJob { const float* in; __nv_bfloat16* out; int R, C; };
struct TransJobs6 { TransJob j[6]; };

__global__ void transpose_all_kernel(TransJobs6 jobs)
{
    __shared__ float tile[32][33];
    const TransJob j = jobs.j[blockIdx.z];
    const int c0 = blockIdx.x * 32, r0 = blockIdx.y * 32;
    if (c0 >= j.C || r0 >= j.R) return;
    const int tx = threadIdx.x, ty = threadIdx.y;
#pragma unroll
    for (int i = ty; i < 32; i += 8)
        tile[i][tx] = j.in[(size_t)(r0 + i) * j.C + c0 + tx];
    __syncthreads();
#pragma unroll
    for (int i = ty; i < 32; i += 8)
        j.out[(size_t)(c0 + i) * j.R + r0 + tx] = __float2bfloat16(tile[tx][i]);
}

// ======================= normalize 16K rows ==================================
__global__ void normalize_cat_kernel(const float* __restrict__ x,
                                     __nv_bfloat16* __restrict__ mp,
                                     __nv_bfloat16* __restrict__ ip)
{
    __shared__ float red[128];
    const int row = blockIdx.x, tid = threadIdx.x;
    const float* p = x + (size_t)row * PROJ;
    __nv_bfloat16* q = (row < B_SZ) ? (mp + (size_t)row * PROJ)
                                    : (ip + (size_t)(row - B_SZ) * PROJ);
    float s = 0.f;
    for (int j = tid; j < PROJ; j += 128) { float v = p[j]; s += v * v; }
    red[tid] = s; __syncthreads();
    for (int off = 64; off > 0; off >>= 1) {
        if (tid < off) red[tid] += red[tid + off];
        __syncthreads();
    }
    const float r = rsqrtf(red[0]);
    for (int j = tid; j < PROJ; j += 128) q[j] = __float2bfloat16(p[j] * r);
}

// ======================= mining + weighted CE =================================
__device__ __forceinline__ unsigned mono(float f)
{
    unsigned u = __float_as_uint(f);
    return (u & 0x80000000u) ? ~u : (u | 0x80000000u);
}

__global__ __launch_bounds__(256)
void mine_loss_kernel(const float* __restrict__ sim, const float* __restrict__ mw,
                      float* __restrict__ ce_out)
{
    __shared__ float    sh[B_SZ];
    __shared__ unsigned hist[2048];
    __shared__ unsigned part[256];
    __shared__ float    red_m[256];
    __shared__ float    red_s[256];
    __shared__ unsigned s_prefix;
    __shared__ int      s_kth;
    __shared__ int      s_cnt;
    __shared__ float    s_vdiag;

    const int bid   = blockIdx.x;
    const int modal = bid >> 13;
    const int row   = bid & (B_SZ - 1);
    const int tid   = threadIdx.x;
    const int lane  = tid & 31;

    const float4* srow4 = (const float4*)(sim + ((size_t)modal * B_SZ + row) * B_SZ);
    for (int j = tid; j < B_SZ / 4; j += 256)
        *(float4*)&sh[j * 4] = srow4[j];
    __syncthreads();

    // pass 1: 2048-bin histogram over top 11 bits
    for (int i = tid; i < 2048; i += 256) hist[i] = 0;
    __syncthreads();
    for (int j = tid; j < B_SZ; j += 256) {
        float s = sh[j];
        unsigned u = (j == row || s > 9.0f) ? 0u : mono(s);
        unsigned bin = u >> 21;
        unsigned peers = __match_any_sync(0xFFFFFFFFu, bin);
        if (lane == (unsigned)(__ffs(peers) - 1))
            atomicAdd(&hist[bin], (unsigned)__popc(peers));
    }
    __syncthreads();

    {
        unsigned loc[8];
        unsigned tot = 0;
#pragma unroll
        for (int i = 7; i >= 0; --i) { tot += hist[tid * 8 + i]; loc[i] = tot; }
        part[tid] = tot;
        __syncthreads();
#pragma unroll
        for (int off = 1; off < 256; off <<= 1) {
            unsigned u2 = (tid + off < 256) ? part[tid + off] : 0u;
            __syncthreads();
            part[tid] += u2;
            __syncthreads();
        }
        const unsigned above = part[tid] - tot;
        if (above < KSEL && loc[0] + above >= KSEL) {
            int bi = 0;
#pragma unroll
            for (int i = 7; i >= 1; --i)
                if (loc[i] + above >= KSEL) { bi = i; break; }
            const unsigned nb = (bi < 7) ? loc[bi + 1] : 0u;
            s_prefix = (unsigned)(tid * 8 + bi) << 21;
            s_kth    = KSEL - (int)(nb + above);
        }
    }
    __syncthreads();
    unsigned prefix = s_prefix;
    int kth = s_kth;
    const unsigned b1 = prefix >> 21;

    // compact boundary-bin candidates
    if (tid == 0) s_cnt = 0;
    __syncthreads();
    for (int j = tid; j < B_SZ; j += 256) {
        float s = sh[j];
        unsigned u = (j == row || s > 9.0f) ? 0u : mono(s);
        if ((u >> 21) == b1) {
            int idx = atomicAdd(&s_cnt, 1);
            if (idx < 2048) hist[idx] = u;
        }
    }
    __syncthreads();
    const int cnt = s_cnt;

    unsigned thr;
    if (cnt <= 2048) {
        unsigned pre2 = prefix, pm2 = 0xFFE00000u;
        int k2 = kth;
        const int      sft[3] = {13, 5, 0};
        const unsigned msk[3] = {0xFFu, 0xFFu, 0x1Fu};
#pragma unroll
        for (int p = 0; p < 3; ++p) {
            part[tid] = 0;
            __syncthreads();
            for (int c = tid; c < cnt; c += 256) {
                unsigned u = hist[c];
                if ((u & pm2) == pre2)
                    atomicAdd(&part[(u >> sft[p]) & msk[p]], 1u);
            }
            __syncthreads();
            const unsigned mycnt = part[tid];
#pragma unroll
            for (int off = 1; off < 256; off <<= 1) {
                unsigned u2 = (tid + off < 256) ? part[tid + off] : 0u;
                __syncthreads();
                part[tid] += u2;
                __syncthreads();
            }
            const unsigned suf = part[tid];
            if (suf >= (unsigned)k2 && (suf - mycnt) < (unsigned)k2) {
                s_prefix = pre2 | ((unsigned)tid << sft[p]);
                s_kth    = k2 - (int)(suf - mycnt);
            }
            __syncthreads();
            pre2 = s_prefix; k2 = s_kth;
            pm2 |= msk[p] << sft[p];
            __syncthreads();
        }
        thr = pre2;
    } else {
        unsigned pm2 = 0xFFE00000u;
        const int      sft[2] = {10, 0};
        const unsigned msk[2] = {0x7FFu, 0x3FFu};
        for (int p = 0; p < 2; ++p) {
            for (int i = tid; i < 2048; i += 256) hist[i] = 0;
            __syncthreads();
            for (int j = tid; j < B_SZ; j += 256) {
                float s = sh[j];
                unsigned u = (j == row || s > 9.0f) ? 0u : mono(s);
                unsigned bin = ((u & pm2) == prefix) ? ((u >> sft[p]) & msk[p]) : 0xFFFFFFFFu;
                unsigned peers = __match_any_sync(0xFFFFFFFFu, bin);
                if (bin != 0xFFFFFFFFu && lane == (unsigned)(__ffs(peers) - 1))
                    atomicAdd(&hist[bin], (unsigned)__popc(peers));
            }
            __syncthreads();
            unsigned loc[8];
            unsigned tot = 0;
#pragma unroll
            for (int i = 7; i >= 0; --i) { tot += hist[tid * 8 + i]; loc[i] = tot; }
            part[tid] = tot;
            __syncthreads();
#pragma unroll
            for (int off = 1; off < 256; off <<= 1) {
                unsigned u2 = (tid + off < 256) ? part[tid + off] : 0u;
                __syncthreads();
                part[tid] += u2;
                __syncthreads();
            }
            const unsigned above = part[tid] - tot;
            if (above < (unsigned)kth && loc[0] + above >= (unsigned)kth) {
                int bi = 0;
#pragma unroll
                for (int i = 7; i >= 1; --i)
                    if (loc[i] + above >= (unsigned)kth) { bi = i; break; }
                const unsigned nb = (bi < 7) ? loc[bi + 1] : 0u;
                s_prefix = prefix | ((unsigned)(tid * 8 + bi) << sft[p]);
                s_kth    = kth - (int)(nb + above);
            }
            __syncthreads();
            prefix = s_prefix; kth = s_kth;
            pm2 |= msk[p] << sft[p];
            __syncthreads();
        }
        thr = prefix;
    }

    // fused weight + online softmax
    float m = -3.402823466e38f, S = 0.f;
    for (int j = tid; j < B_SZ; j += 256) {
        float s = sh[j];
        bool diag  = (j == row);
        bool noise = (!diag) && (s > 9.0f);
        float w;
        if (noise)                        w = 0.5f;
        else if (!diag && mono(s) >= thr) w = 1.5f;
        else                              w = 1.0f;
        float v = s * w;
        if (diag) s_vdiag = v;
        if (v > m) { S = S * __expf(m - v) + 1.f; m = v; }
        else       { S += __expf(v - m); }
    }
    red_m[tid] = m; red_s[tid] = S;
    __syncthreads();
    for (int off = 128; off > 0; off >>= 1) {
        if (tid < off) {
            float m1 = red_m[tid], m2 = red_m[tid + off];
            float S1 = red_s[tid], S2 = red_s[tid + off];
            float M = fmaxf(m1, m2);
            red_s[tid] = S1 * __expf(m1 - M) + S2 * __expf(m2 - M);
            red_m[tid] = M;
        }
        __syncthreads();
    }
    if (tid == 0) {
        float lse = red_m[0] + __logf(red_s[0]);
        float ce  = lse - s_vdiag;
        ce_out[modal * B_SZ + row] = ce * mw[(size_t)row * 2 + modal];
    }
}

__global__ void finalize_kernel(const float* __restrict__ ce, float* __restrict__ out)
{
    __shared__ float red[256];
    const int tid = threadIdx.x;
    float s = 0.f;
    for (int j = tid; j < 2 * B_SZ; j += 256) s += ce[j];
    red[tid] = s; __syncthreads();
    for (int off = 128; off > 0; off >>= 1) {
        if (tid < off) red[tid] += red[tid + off];
        __syncthreads();
    }
    if (tid == 0) out[0] = red[0] * (0.5f / (float)B_SZ);
}

// ======================= launch ==============================================
extern "C" void kernel_launch(void* const* d_in, const int* in_sizes, int n_in,
                              void* d_out, int out_size)
{
    const float* id_emb = (const float*)d_in[0];
    const float* text   = (const float*)d_in[1];
    const float* vis    = (const float*)d_in[2];
    const float* mw     = (const float*)d_in[3];
    const float* Wa_t = (const float*)d_in[4];  const float* ba_t = (const float*)d_in[5];
    const float* Wa_v = (const float*)d_in[6];  const float* ba_v = (const float*)d_in[7];
    const float* W1_t = (const float*)d_in[8];  const float* b1_t = (const float*)d_in[9];
    const float* W2_t = (const float*)d_in[10]; const float* b2_t = (const float*)d_in[11];
    const float* W1_v = (const float*)d_in[12]; const float* b1_v = (const float*)d_in[13];
    const float* W2_v = (const float*)d_in[14]; const float* b2_v = (const float*)d_in[15];

    __nv_bfloat16 *wa_t, *wa_v, *w1_t, *w1_v, *w2_t, *w2_v;
    __nv_bfloat16 *cat, *hcat, *mproj, *iproj;
    float *pcat, *sim, *ce;
    cudaGetSymbolAddress((void**)&wa_t, g_Wa_t);   cudaGetSymbolAddress((void**)&wa_v, g_Wa_v);
    cudaGetSymbolAddress((void**)&w1_t, g_W1_t);   cudaGetSymbolAddress((void**)&w1_v, g_W1_v);
    cudaGetSymbolAddress((void**)&w2_t, g_W2_t);   cudaGetSymbolAddress((void**)&w2_v, g_W2_v);
    cudaGetSymbolAddress((void**)&cat,  g_cat);    cudaGetSymbolAddress((void**)&hcat, g_hcat);
    cudaGetSymbolAddress((void**)&pcat, g_pcat);
    cudaGetSymbolAddress((void**)&mproj, g_mproj); cudaGetSymbolAddress((void**)&iproj, g_iproj);
    cudaGetSymbolAddress((void**)&sim, g_sim);     cudaGetSymbolAddress((void**)&ce, g_ce);

    cudaFuncSetAttribute((const void*)hmma_gemm<false, true, true, false, true>,
                         cudaFuncAttributeMaxDynamicSharedMemorySize, TC_DSMEM);
    cudaFuncSetAttribute((const void*)hmma_gemm<true, true, true, false, false>,
                         cudaFuncAttributeMaxDynamicSharedMemorySize, TC_DSMEM);
    cudaFuncSetAttribute((const void*)hmma_gemm<false, true, false, false, false>,
                         cudaFuncAttributeMaxDynamicSharedMemorySize, TC_DSMEM);
    cudaFuncSetAttribute((const void*)hmma_gemm<false, false, false, true, false>,
                         cudaFuncAttributeMaxDynamicSharedMemorySize, TC_DSMEM);

    {
        TransJobs6 jobs = {{
            { Wa_t, wa_t, 768,  HID  },
            { Wa_v, wa_v, 2048, HID  },
            { W1_t, w1_t, HID,  HID  },
            { W1_v, w1_v, HID,  HID  },
            { W2_t, w2_t, HID,  PROJ },
            { W2_v, w2_v, HID,  PROJ },
        }};
        transpose_all_kernel<<<dim3(HID / 32, 2048 / 32, 6), dim3(32, 8)>>>(jobs);
    }
    // id embeddings -> bf16 into upper half of cat (once)
    cvt_bf16_kernel<<<(B_SZ * HID / 4 + 255) / 256, 256>>>(
        id_emb, cat + (size_t)B_SZ * HID, B_SZ * HID / 4);

    struct Modal {
        const float* f; int kf;
        const __nv_bfloat16 *wa, *w1, *w2;
        const float *ba, *b1, *b2;
    };
    const Modal ms[2] = {
        { text,  768, wa_t, w1_t, w2_t, ba_t, b1_t, b2_t },
        { vis,  2048, wa_v, w1_v, w2_v, ba_v, b1_v, b2_v },
    };

    for (int m = 0; m < 2; m++) {
        const int KF = ms[m].kf;
        // adapter: fp32 input converted in-loader (no separate cvt launch)
        hmma_gemm<false, true, true, false, true><<<dim3(HID / 128, B_SZ / 128), 256, TC_DSMEM>>>(
            (const __nv_bfloat16*)ms[m].f, ms[m].wa, ms[m].ba, cat, B_SZ, HID, KF, 1.f);
        hmma_gemm<true, true, true, false, false><<<dim3(HID / 128, 2 * B_SZ / 128), 256, TC_DSMEM>>>(
            cat, ms[m].w1, ms[m].b1, hcat, 2 * B_SZ, HID, HID, 1.f);
        hmma_gemm<false, true, false, false, false><<<dim3(PROJ / 128, 2 * B_SZ / 128), 256, TC_DSMEM>>>(
            hcat, ms[m].w2, ms[m].b2, pcat, 2 * B_SZ, PROJ, HID, 1.f);
        normalize_cat_kernel<<<2 * B_SZ, 128>>>(
            pcat, mproj + (size_t)m * B_SZ * PROJ, iproj + (size_t)m * B_SZ * PROJ);
    }

    // batched sim GEMM over both modalities, then batched mining
    hmma_gemm<false, false, false, true, false><<<dim3(B_SZ / 128, B_SZ / 128, 2), 256, TC_DSMEM>>>(
        iproj, mproj, nullptr, sim, B_SZ, B_SZ, PROJ, 10.0f);
    mine_loss_kernel<<<2 * B_SZ, 256>>>(sim, mw, ce);
    finalize_kernel<<<1, 256>>>(ce, (float*)d_out);
}

// round 16
// speedup vs baseline: 1.0517x; 1.0517x over previous
#include <cuda_runtime.h>
#include <cuda_bf16.h>
#include <cstdint>

#define B_SZ 8192
#define HID  1024
#define PROJ 512
#define KSEL 4096

// ======================= helpers =============================================
__device__ __forceinline__ uint32_t smem_to_u32(const void* p) {
    uint32_t a;
    asm("{ .reg .u64 t; cvta.to.shared.u64 t, %1; cvt.u32.u64 %0, t; }"
        : "=r"(a) : "l"(p));
    return a;
}
#define SW128(off) ((off) ^ (((off) >> 3) & 0x70))

__device__ __forceinline__ void cp_async16(uint32_t dst, const void* src) {
    asm volatile("cp.async.cg.shared.global [%0], [%1], 16;"
                 :: "r"(dst), "l"(src) : "memory");
}
__device__ __forceinline__ void ldsm_x4(uint32_t& r0, uint32_t& r1,
                                        uint32_t& r2, uint32_t& r3, uint32_t addr) {
    asm volatile("ldmatrix.sync.aligned.m8n8.x4.shared.b16 {%0,%1,%2,%3}, [%4];"
                 : "=r"(r0), "=r"(r1), "=r"(r2), "=r"(r3) : "r"(addr));
}
__device__ __forceinline__ void mma_bf16(float* c, const uint32_t* a,
                                         uint32_t b0, uint32_t b1) {
    asm volatile(
        "mma.sync.aligned.m16n8k16.row.col.f32.bf16.bf16.f32 "
        "{%0,%1,%2,%3}, {%4,%5,%6,%7}, {%8,%9}, {%0,%1,%2,%3};"
        : "+f"(c[0]), "+f"(c[1]), "+f"(c[2]), "+f"(c[3])
        : "r"(a[0]), "r"(a[1]), "r"(a[2]), "r"(a[3]), "r"(b0), "r"(b1));
}

// ======================= scratch (device globals) ============================
__device__ __align__(16) __nv_bfloat16 g_Wa_t[HID * 768];
__device__ __align__(16) __nv_bfloat16 g_Wa_v[HID * 2048];
__device__ __align__(16) __nv_bfloat16 g_W1_t[HID * HID];
__device__ __align__(16) __nv_bfloat16 g_W1_v[HID * HID];
__device__ __align__(16) __nv_bfloat16 g_W2_t[PROJ * HID];
__device__ __align__(16) __nv_bfloat16 g_W2_v[PROJ * HID];
__device__ __align__(16) __nv_bfloat16 g_in_bf[B_SZ * 2048];
__device__ __align__(16) __nv_bfloat16 g_cat [2 * B_SZ * HID];
__device__ __align__(16) __nv_bfloat16 g_hcat[2 * B_SZ * HID];
__device__ __align__(16) float         g_pcat[2 * B_SZ * PROJ];
__device__ __align__(16) __nv_bfloat16 g_mproj[2 * B_SZ * PROJ];
__device__ __align__(16) __nv_bfloat16 g_iproj[2 * B_SZ * PROJ];
__device__ float g_sim[2 * (size_t)B_SZ * B_SZ];
__device__ float g_ce[2 * B_SZ];

// ======================= HMMA GEMM (128x128 CTA tile, 2 stages, 2 CTA/SM) ====
static constexpr int STAGES   = 2;
static constexpr int TC_DSMEM = STAGES * 32 * 1024 + 1024;

template <bool RELU, bool BIAS, bool OUT_BF16, bool ZBATCH>
__global__ __launch_bounds__(256, 2)
void hmma_gemm(const __nv_bfloat16* __restrict__ A, const __nv_bfloat16* __restrict__ Bw,
               const float* __restrict__ bias, void* __restrict__ Cout,
               int M, int N, int K, float scale)
{
    extern __shared__ char dsm[];
    const uint32_t base_u  = smem_to_u32(dsm);
    const uint32_t tiles_u = (base_u + 1023u) & ~1023u;

    if (ZBATCH) {
        const size_t zo = (size_t)blockIdx.z;
        A    += zo * B_SZ * PROJ;
        Bw   += zo * B_SZ * PROJ;
        Cout  = (float*)Cout + zo * (size_t)B_SZ * B_SZ;
    }

    const int tid  = threadIdx.x;
    const int wid  = tid >> 5, lane = tid & 31;
    const int wm   = wid >> 2, wn = wid & 3;
    const int bm   = blockIdx.y * 128, bn = blockIdx.x * 128;
    const int nsteps = K >> 6;

    float acc[4][4][4];
#pragma unroll
    for (int i = 0; i < 4; i++)
#pragma unroll
        for (int j = 0; j < 4; j++)
#pragma unroll
            for (int r = 0; r < 4; r++) acc[i][j][r] = 0.f;

    const int lr = tid >> 3;
    const int lc = tid & 7;

    auto load_stage = [&](int buf, int k0) {
        const uint32_t tA = tiles_u + (uint32_t)buf * 32768u;
        const uint32_t tB = tA + 16384u;
#pragma unroll
        for (int h = 0; h < 4; h++) {
            int r = lr + h * 32;
            uint32_t sw = SW128((uint32_t)(r * 128 + lc * 16));
            cp_async16(tA + sw, A  + (size_t)(bm + r) * K + k0 + lc * 8);
            cp_async16(tB + sw, Bw + (size_t)(bn + r) * K + k0 + lc * 8);
        }
        asm volatile("cp.async.commit_group;" ::: "memory");
    };

    const int a_row  = wm * 64 + (lane & 15);
    const int a_colb = (lane >> 4) << 4;
    const int b_row0 = wn * 32 + (lane & 7) + ((lane >> 4) << 3);
    const int b_colb = ((lane >> 3) & 1) << 4;

    auto ld_frags = [&](uint32_t tA, uint32_t tB, int kk,
                        uint32_t a[4][4], uint32_t bf[2][4]) {
        const int kb = kk * 32;
#pragma unroll
        for (int mt = 0; mt < 4; ++mt)
            ldsm_x4(a[mt][0], a[mt][1], a[mt][2], a[mt][3],
                    tA + SW128((uint32_t)((a_row + mt * 16) * 128 + kb + a_colb)));
#pragma unroll
        for (int np = 0; np < 2; ++np)
            ldsm_x4(bf[np][0], bf[np][1], bf[np][2], bf[np][3],
                    tB + SW128((uint32_t)((b_row0 + np * 16) * 128 + kb + b_colb)));
    };

    load_stage(0, 0);

    uint32_t afr[2][4][4], bfr[2][2][4];

    for (int s = 0; s < nsteps; ++s) {
        if (s + 1 < nsteps) {
            load_stage((s + 1) & 1, (s + 1) << 6);
            asm volatile("cp.async.wait_group 1;" ::: "memory");
        } else {
            asm volatile("cp.async.wait_group 0;" ::: "memory");
        }
        __syncthreads();

        const uint32_t tA = tiles_u + (uint32_t)(s & 1) * 32768u;
        const uint32_t tB = tA + 16384u;

        ld_frags(tA, tB, 0, afr[0], bfr[0]);
#pragma unroll
        for (int kk = 0; kk < 4; ++kk) {
            const int cur = kk & 1;
            if (kk < 3) ld_frags(tA, tB, kk + 1, afr[cur ^ 1], bfr[cur ^ 1]);
#pragma unroll
            for (int mt = 0; mt < 4; ++mt)
#pragma unroll
                for (int nt = 0; nt < 4; ++nt)
                    mma_bf16(acc[mt][nt], afr[cur][mt],
                             bfr[cur][nt >> 1][(nt & 1) * 2],
                             bfr[cur][nt >> 1][(nt & 1) * 2 + 1]);
        }
        __syncthreads();
    }

    const int g = lane >> 2, tg = lane & 3;
#pragma unroll
    for (int mt = 0; mt < 4; ++mt) {
#pragma unroll
        for (int nt = 0; nt < 4; ++nt) {
            const int m0 = bm + wm * 64 + mt * 16 + g;
            const int n0 = bn + wn * 32 + nt * 8 + tg * 2;
            float v0 = acc[mt][nt][0], v1 = acc[mt][nt][1];
            float v2 = acc[mt][nt][2], v3 = acc[mt][nt][3];
            if (BIAS) {
                float bb0 = bias[n0], bb1 = bias[n0 + 1];
                v0 += bb0; v1 += bb1; v2 += bb0; v3 += bb1;
            }
            v0 *= scale; v1 *= scale; v2 *= scale; v3 *= scale;
            if (RELU) {
                v0 = fmaxf(v0, 0.f); v1 = fmaxf(v1, 0.f);
                v2 = fmaxf(v2, 0.f); v3 = fmaxf(v3, 0.f);
            }
            if (OUT_BF16) {
                __nv_bfloat16* C = (__nv_bfloat16*)Cout;
                *(__nv_bfloat162*)(C + (size_t)m0 * N + n0)       = __floats2bfloat162_rn(v0, v1);
                *(__nv_bfloat162*)(C + (size_t)(m0 + 8) * N + n0) = __floats2bfloat162_rn(v2, v3);
            } else {
                float* C = (float*)Cout;
                *(float2*)(C + (size_t)m0 * N + n0)       = make_float2(v0, v1);
                *(float2*)(C + (size_t)(m0 + 8) * N + n0) = make_float2(v2, v3);
            }
        }
    }
}

// ======================= conversion / transpose ==============================
__global__ void cvt_bf16_kernel(const float* __restrict__ in,
                                __nv_bfloat16* __restrict__ out, int n4)
{
    int i = blockIdx.x * blockDim.x + threadIdx.x;
    if (i < n4) {
        float4 v = *(const float4*)(in + i * 4);
        __nv_bfloat162* o = (__nv_bfloat162*)(out + i * 4);
        o[0] = __floats2bfloat162_rn(v.x, v.y);
        o[1] = __floats2bfloat162_rn(v.z, v.w);
    }
}

struct TransJob { const float* in; __nv_bfloat16* out; int R, C; };
struct TransJobs6 { TransJob j[6]; };

__global__ void transpose_all_kernel(TransJobs6 jobs)
{
    __shared__ float tile[32][33];
    const TransJob j = jobs.j[blockIdx.z];
    const int c0 = blockIdx.x * 32, r0 = blockIdx.y * 32;
    if (c0 >= j.C || r0 >= j.R) return;
    const int tx = threadIdx.x, ty = threadIdx.y;
#pragma unroll
    for (int i = ty; i < 32; i += 8)
        tile[i][tx] = j.in[(size_t)(r0 + i) * j.C + c0 + tx];
    __syncthreads();
#pragma unroll
    for (int i = ty; i < 32; i += 8)
        j.out[(size_t)(c0 + i) * j.R + r0 + tx] = __float2bfloat16(tile[tx][i]);
}

// ======================= normalize 16K rows ==================================
__global__ void normalize_cat_kernel(const float* __restrict__ x,
                                     __nv_bfloat16* __restrict__ mp,
                                     __nv_bfloat16* __restrict__ ip)
{
    __shared__ float red[128];
    const int row = blockIdx.x, tid = threadIdx.x;
    const float* p = x + (size_t)row * PROJ;
    __nv_bfloat16* q = (row < B_SZ) ? (mp + (size_t)row * PROJ)
                                    : (ip + (size_t)(row - B_SZ) * PROJ);
    float s = 0.f;
    for (int j = tid; j < PROJ; j += 128) { float v = p[j]; s += v * v; }
    red[tid] = s; __syncthreads();
    for (int off = 64; off > 0; off >>= 1) {
        if (tid < off) red[tid] += red[tid + off];
        __syncthreads();
    }
    const float r = rsqrtf(red[0]);
    for (int j = tid; j < PROJ; j += 128) q[j] = __float2bfloat16(p[j] * r);
}

// ======================= mining + weighted CE (v7: fused load+histogram) ======
__device__ __forceinline__ unsigned mono(float f)
{
    unsigned u = __float_as_uint(f);
    return (u & 0x80000000u) ? ~u : (u | 0x80000000u);
}

__global__ __launch_bounds__(256)
void mine_loss_kernel(const float* __restrict__ sim, const float* __restrict__ mw,
                      float* __restrict__ ce_out)
{
    __shared__ float    sh[B_SZ];
    __shared__ unsigned hist[2048];
    __shared__ unsigned part[256];
    __shared__ float    red_m[256];
    __shared__ float    red_s[256];
    __shared__ unsigned s_prefix;
    __shared__ int      s_kth;
    __shared__ int      s_cnt;
    __shared__ float    s_vdiag;

    const int bid   = blockIdx.x;
    const int modal = bid >> 13;
    const int row   = bid & (B_SZ - 1);
    const int tid   = threadIdx.x;
    const int lane  = tid & 31;

    // zero histogram BEFORE the load sweep so load+hist can fuse
    for (int i = tid; i < 2048; i += 256) hist[i] = 0;
    __syncthreads();

    // fused: gmem row load -> smem + pass-1 histogram from registers
    const float4* srow4 = (const float4*)(sim + ((size_t)modal * B_SZ + row) * B_SZ);
    for (int j4 = tid; j4 < B_SZ / 4; j4 += 256) {
        const float4 v4 = srow4[j4];
        *(float4*)&sh[j4 * 4] = v4;
        const float vs[4] = { v4.x, v4.y, v4.z, v4.w };
#pragma unroll
        for (int k = 0; k < 4; ++k) {
            const int j = j4 * 4 + k;
            unsigned u = (j == row || vs[k] > 9.0f) ? 0u : mono(vs[k]);
            unsigned bin = u >> 21;
            unsigned peers = __match_any_sync(0xFFFFFFFFu, bin);
            if (lane == (unsigned)(__ffs(peers) - 1))
                atomicAdd(&hist[bin], (unsigned)__popc(peers));
        }
    }
    __syncthreads();

    // parallel suffix select over 2048 bins (8 per thread)
    {
        unsigned loc[8];
        unsigned tot = 0;
#pragma unroll
        for (int i = 7; i >= 0; --i) { tot += hist[tid * 8 + i]; loc[i] = tot; }
        part[tid] = tot;
        __syncthreads();
#pragma unroll
        for (int off = 1; off < 256; off <<= 1) {
            unsigned u2 = (tid + off < 256) ? part[tid + off] : 0u;
            __syncthreads();
            part[tid] += u2;
            __syncthreads();
        }
        const unsigned above = part[tid] - tot;
        if (above < KSEL && loc[0] + above >= KSEL) {
            int bi = 0;
#pragma unroll
            for (int i = 7; i >= 1; --i)
                if (loc[i] + above >= KSEL) { bi = i; break; }
            const unsigned nb = (bi < 7) ? loc[bi + 1] : 0u;
            s_prefix = (unsigned)(tid * 8 + bi) << 21;
            s_kth    = KSEL - (int)(nb + above);
        }
    }
    __syncthreads();
    unsigned prefix = s_prefix;
    int kth = s_kth;
    const unsigned b1 = prefix >> 21;

    // compact boundary-bin candidates into hist[]
    if (tid == 0) s_cnt = 0;
    __syncthreads();
    for (int j = tid; j < B_SZ; j += 256) {
        float s = sh[j];
        unsigned u = (j == row || s > 9.0f) ? 0u : mono(s);
        if ((u >> 21) == b1) {
            int idx = atomicAdd(&s_cnt, 1);
            if (idx < 2048) hist[idx] = u;
        }
    }
    __syncthreads();
    const int cnt = s_cnt;

    unsigned thr;
    if (cnt <= 2048) {
        unsigned pre2 = prefix, pm2 = 0xFFE00000u;
        int k2 = kth;
        const int      sft[3] = {13, 5, 0};
        const unsigned msk[3] = {0xFFu, 0xFFu, 0x1Fu};
#pragma unroll
        for (int p = 0; p < 3; ++p) {
            part[tid] = 0;
            __syncthreads();
            for (int c = tid; c < cnt; c += 256) {
                unsigned u = hist[c];
                if ((u & pm2) == pre2)
                    atomicAdd(&part[(u >> sft[p]) & msk[p]], 1u);
            }
            __syncthreads();
            const unsigned mycnt = part[tid];
#pragma unroll
            for (int off = 1; off < 256; off <<= 1) {
                unsigned u2 = (tid + off < 256) ? part[tid + off] : 0u;
                __syncthreads();
                part[tid] += u2;
                __syncthreads();
            }
            const unsigned suf = part[tid];
            if (suf >= (unsigned)k2 && (suf - mycnt) < (unsigned)k2) {
                s_prefix = pre2 | ((unsigned)tid << sft[p]);
                s_kth    = k2 - (int)(suf - mycnt);
            }
            __syncthreads();
            pre2 = s_prefix; k2 = s_kth;
            pm2 |= msk[p] << sft[p];
            __syncthreads();
        }
        thr = pre2;
    } else {
        // fallback: full passes over bits [10,21) and [0,10)
        unsigned pm2 = 0xFFE00000u;
        const int      sft[2] = {10, 0};
        const unsigned msk[2] = {0x7FFu, 0x3FFu};
        for (int p = 0; p < 2; ++p) {
            for (int i = tid; i < 2048; i += 256) hist[i] = 0;
            __syncthreads();
            for (int j = tid; j < B_SZ; j += 256) {
                float s = sh[j];
                unsigned u = (j == row || s > 9.0f) ? 0u : mono(s);
                unsigned bin = ((u & pm2) == prefix) ? ((u >> sft[p]) & msk[p]) : 0xFFFFFFFFu;
                unsigned peers = __match_any_sync(0xFFFFFFFFu, bin);
                if (bin != 0xFFFFFFFFu && lane == (unsigned)(__ffs(peers) - 1))
                    atomicAdd(&hist[bin], (unsigned)__popc(peers));
            }
            __syncthreads();
            unsigned loc[8];
            unsigned tot = 0;
#pragma unroll
            for (int i = 7; i >= 0; --i) { tot += hist[tid * 8 + i]; loc[i] = tot; }
            part[tid] = tot;
            __syncthreads();
#pragma unroll
            for (int off = 1; off < 256; off <<= 1) {
                unsigned u2 = (tid + off < 256) ? part[tid + off] : 0u;
                __syncthreads();
                part[tid] += u2;
                __syncthreads();
            }
            const unsigned above = part[tid] - tot;
            if (above < (unsigned)kth && loc[0] + above >= (unsigned)kth) {
                int bi = 0;
#pragma unroll
                for (int i = 7; i >= 1; --i)
                    if (loc[i] + above >= (unsigned)kth) { bi = i; break; }
                const unsigned nb = (bi < 7) ? loc[bi + 1] : 0u;
                s_prefix = prefix | ((unsigned)(tid * 8 + bi) << sft[p]);
                s_kth    = kth - (int)(nb + above);
            }
            __syncthreads();
            prefix = s_prefix; kth = s_kth;
            pm2 |= msk[p] << sft[p];
            __syncthreads();
        }
        thr = prefix;
    }

    // fused weight + online softmax
    float m = -3.402823466e38f, S = 0.f;
    for (int j = tid; j < B_SZ; j += 256) {
        float s = sh[j];
        bool diag  = (j == row);
        bool noise = (!diag) && (s > 9.0f);
        float w;
        if (noise)                        w = 0.5f;
        else if (!diag && mono(s) >= thr) w = 1.5f;
        else                              w = 1.0f;
        float v = s * w;
        if (diag) s_vdiag = v;
        if (v > m) { S = S * __expf(m - v) + 1.f; m = v; }
        else       { S += __expf(v - m); }
    }
    red_m[tid] = m; red_s[tid] = S;
    __syncthreads();
    for (int off = 128; off > 0; off >>= 1) {
        if (tid < off) {
            float m1 = red_m[tid], m2 = red_m[tid + off];
            float S1 = red_s[tid], S2 = red_s[tid + off];
            float M = fmaxf(m1, m2);
            red_s[tid] = S1 * __expf(m1 - M) + S2 * __expf(m2 - M);
            red_m[tid] = M;
        }
        __syncthreads();
    }
    if (tid == 0) {
        float lse = red_m[0] + __logf(red_s[0]);
        float ce  = lse - s_vdiag;
        ce_out[modal * B_SZ + row] = ce * mw[(size_t)row * 2 + modal];
    }
}

__global__ void finalize_kernel(const float* __restrict__ ce, float* __restrict__ out)
{
    __shared__ float red[256];
    const int tid = threadIdx.x;
    float s = 0.f;
    for (int j = tid; j < 2 * B_SZ; j += 256) s += ce[j];
    red[tid] = s; __syncthreads();
    for (int off = 128; off > 0; off >>= 1) {
        if (tid < off) red[tid] += red[tid + off];
        __syncthreads();
    }
    if (tid == 0) out[0] = red[0] * (0.5f / (float)B_SZ);
}

// ======================= launch ==============================================
extern "C" void kernel_launch(void* const* d_in, const int* in_sizes, int n_in,
                              void* d_out, int out_size)
{
    const float* id_emb = (const float*)d_in[0];
    const float* text   = (const float*)d_in[1];
    const float* vis    = (const float*)d_in[2];
    const float* mw     = (const float*)d_in[3];
    const float* Wa_t = (const float*)d_in[4];  const float* ba_t = (const float*)d_in[5];
    const float* Wa_v = (const float*)d_in[6];  const float* ba_v = (const float*)d_in[7];
    const float* W1_t = (const float*)d_in[8];  const float* b1_t = (const float*)d_in[9];
    const float* W2_t = (const float*)d_in[10]; const float* b2_t = (const float*)d_in[11];
    const float* W1_v = (const float*)d_in[12]; const float* b1_v = (const float*)d_in[13];
    const float* W2_v = (const float*)d_in[14]; const float* b2_v = (const float*)d_in[15];

    __nv_bfloat16 *wa_t, *wa_v, *w1_t, *w1_v, *w2_t, *w2_v;
    __nv_bfloat16 *in_bf, *cat, *hcat, *mproj, *iproj;
    float *pcat, *sim, *ce;
    cudaGetSymbolAddress((void**)&wa_t, g_Wa_t);   cudaGetSymbolAddress((void**)&wa_v, g_Wa_v);
    cudaGetSymbolAddress((void**)&w1_t, g_W1_t);   cudaGetSymbolAddress((void**)&w1_v, g_W1_v);
    cudaGetSymbolAddress((void**)&w2_t, g_W2_t);   cudaGetSymbolAddress((void**)&w2_v, g_W2_v);
    cudaGetSymbolAddress((void**)&in_bf, g_in_bf);
    cudaGetSymbolAddress((void**)&cat,  g_cat);    cudaGetSymbolAddress((void**)&hcat, g_hcat);
    cudaGetSymbolAddress((void**)&pcat, g_pcat);
    cudaGetSymbolAddress((void**)&mproj, g_mproj); cudaGetSymbolAddress((void**)&iproj, g_iproj);
    cudaGetSymbolAddress((void**)&sim, g_sim);     cudaGetSymbolAddress((void**)&ce, g_ce);

    cudaFuncSetAttribute((const void*)hmma_gemm<false, true, true, false>,
                         cudaFuncAttributeMaxDynamicSharedMemorySize, TC_DSMEM);
    cudaFuncSetAttribute((const void*)hmma_gemm<true, true, true, false>,
                         cudaFuncAttributeMaxDynamicSharedMemorySize, TC_DSMEM);
    cudaFuncSetAttribute((const void*)hmma_gemm<false, true, false, false>,
                         cudaFuncAttributeMaxDynamicSharedMemorySize, TC_DSMEM);
    cudaFuncSetAttribute((const void*)hmma_gemm<false, false, false, true>,
                         cudaFuncAttributeMaxDynamicSharedMemorySize, TC_DSMEM);

    {
        TransJobs6 jobs = {{
            { Wa_t, wa_t, 768,  HID  },
            { Wa_v, wa_v, 2048, HID  },
            { W1_t, w1_t, HID,  HID  },
            { W1_v, w1_v, HID,  HID  },
            { W2_t, w2_t, HID,  PROJ },
            { W2_v, w2_v, HID,  PROJ },
        }};
        transpose_all_kernel<<<dim3(HID / 32, 2048 / 32, 6), dim3(32, 8)>>>(jobs);
    }
    cvt_bf16_kernel<<<(B_SZ * HID / 4 + 255) / 256, 256>>>(
        id_emb, cat + (size_t)B_SZ * HID, B_SZ * HID / 4);

    struct Modal {
        const float* f; int kf;
        const __nv_bfloat16 *wa, *w1, *w2;
        const float *ba, *b1, *b2;
    };
    const Modal ms[2] = {
        { text,  768, wa_t, w1_t, w2_t, ba_t, b1_t, b2_t },
        { vis,  2048, wa_v, w1_v, w2_v, ba_v, b1_v, b2_v },
    };

    for (int m = 0; m < 2; m++) {
        const int KF = ms[m].kf;
        cvt_bf16_kernel<<<(B_SZ * KF / 4 + 255) / 256, 256>>>(ms[m].f, in_bf, B_SZ * KF / 4);
        hmma_gemm<false, true, true, false><<<dim3(HID / 128, B_SZ / 128), 256, TC_DSMEM>>>(
            in_bf, ms[m].wa, ms[m].ba, cat, B_SZ, HID, KF, 1.f);
        hmma_gemm<true, true, true, false><<<dim3(HID / 128, 2 * B_SZ / 128), 256, TC_DSMEM>>>(
            cat, ms[m].w1, ms[m].b1, hcat, 2 * B_SZ, HID, HID, 1.f);
        hmma_gemm<false, true, false, false><<<dim3(PROJ / 128, 2 * B_SZ / 128), 256, TC_DSMEM>>>(
            hcat, ms[m].w2, ms[m].b2, pcat, 2 * B_SZ, PROJ, HID, 1.f);
        normalize_cat_kernel<<<2 * B_SZ, 128>>>(
            pcat, mproj + (size_t)m * B_SZ * PROJ, iproj + (size_t)m * B_SZ * PROJ);
    }

    hmma_gemm<false, false, false, true><<<dim3(B_SZ / 128, B_SZ / 128, 2), 256, TC_DSMEM>>>(
        iproj, mproj, nullptr, sim, B_SZ, B_SZ, PROJ, 10.0f);
    mine_loss_kernel<<<2 * B_SZ, 256>>>(sim, mw, ce);
    finalize_kernel<<<1, 256>>>(ce, (float*)d_out);
}

// round 17
// speedup vs baseline: 1.0619x; 1.0097x over previous
#include <cuda_runtime.h>
#include <cuda_bf16.h>
#include <cstdint>

#define B_SZ 8192
#define HID  1024
#define PROJ 512
#define KSEL 4096

// ======================= helpers =============================================
__device__ __forceinline__ uint32_t smem_to_u32(const void* p) {
    uint32_t a;
    asm("{ .reg .u64 t; cvta.to.shared.u64 t, %1; cvt.u32.u64 %0, t; }"
        : "=r"(a) : "l"(p));
    return a;
}
#define SW128(off) ((off) ^ (((off) >> 3) & 0x70))

__device__ __forceinline__ void cp_async16(uint32_t dst, const void* src) {
    asm volatile("cp.async.cg.shared.global [%0], [%1], 16;"
                 :: "r"(dst), "l"(src) : "memory");
}
__device__ __forceinline__ void ldsm_x4(uint32_t& r0, uint32_t& r1,
                                        uint32_t& r2, uint32_t& r3, uint32_t addr) {
    asm volatile("ldmatrix.sync.aligned.m8n8.x4.shared.b16 {%0,%1,%2,%3}, [%4];"
                 : "=r"(r0), "=r"(r1), "=r"(r2), "=r"(r3) : "r"(addr));
}
__device__ __forceinline__ void mma_bf16(float* c, const uint32_t* a,
                                         uint32_t b0, uint32_t b1) {
    asm volatile(
        "mma.sync.aligned.m16n8k16.row.col.f32.bf16.bf16.f32 "
        "{%0,%1,%2,%3}, {%4,%5,%6,%7}, {%8,%9}, {%0,%1,%2,%3};"
        : "+f"(c[0]), "+f"(c[1]), "+f"(c[2]), "+f"(c[3])
        : "r"(a[0]), "r"(a[1]), "r"(a[2]), "r"(a[3]), "r"(b0), "r"(b1));
}

// ======================= scratch (device globals) ============================
__device__ __align__(16) __nv_bfloat16 g_Wa_t[HID * 768];
__device__ __align__(16) __nv_bfloat16 g_Wa_v[HID * 2048];
__device__ __align__(16) __nv_bfloat16 g_W1_t[HID * HID];
__device__ __align__(16) __nv_bfloat16 g_W1_v[HID * HID];
__device__ __align__(16) __nv_bfloat16 g_W2_t[PROJ * HID];
__device__ __align__(16) __nv_bfloat16 g_W2_v[PROJ * HID];
__device__ __align__(16) __nv_bfloat16 g_in_bf[B_SZ * 2048];
__device__ __align__(16) __nv_bfloat16 g_cat [2 * B_SZ * HID];
__device__ __align__(16) __nv_bfloat16 g_hcat[2 * B_SZ * HID];
__device__ __align__(16) float         g_pcat[2 * B_SZ * PROJ];
__device__ __align__(16) __nv_bfloat16 g_mproj[2 * B_SZ * PROJ];
__device__ __align__(16) __nv_bfloat16 g_iproj[2 * B_SZ * PROJ];
__device__ float g_sim[2 * (size_t)B_SZ * B_SZ];
__device__ float g_ce[2 * B_SZ];

// ======================= HMMA GEMM (128x128 CTA tile, 2 stages, 2 CTA/SM) ====
static constexpr int STAGES   = 2;
static constexpr int TC_DSMEM = STAGES * 32 * 1024 + 1024;

template <bool RELU, bool BIAS, bool OUT_BF16, bool ZBATCH>
__global__ __launch_bounds__(256, 2)
void hmma_gemm(const __nv_bfloat16* __restrict__ A, const __nv_bfloat16* __restrict__ Bw,
               const float* __restrict__ bias, void* __restrict__ Cout,
               int M, int N, int K, float scale)
{
    extern __shared__ char dsm[];
    const uint32_t base_u  = smem_to_u32(dsm);
    const uint32_t tiles_u = (base_u + 1023u) & ~1023u;

    if (ZBATCH) {
        const size_t zo = (size_t)blockIdx.z;
        A    += zo * B_SZ * PROJ;
        Bw   += zo * B_SZ * PROJ;
        Cout  = (float*)Cout + zo * (size_t)B_SZ * B_SZ;
    }

    const int tid  = threadIdx.x;
    const int wid  = tid >> 5, lane = tid & 31;
    const int wm   = wid >> 2, wn = wid & 3;
    const int bm   = blockIdx.y * 128, bn = blockIdx.x * 128;
    const int nsteps = K >> 6;

    float acc[4][4][4];
#pragma unroll
    for (int i = 0; i < 4; i++)
#pragma unroll
        for (int j = 0; j < 4; j++)
#pragma unroll
            for (int r = 0; r < 4; r++) acc[i][j][r] = 0.f;

    const int lr = tid >> 3;
    const int lc = tid & 7;

    auto load_stage = [&](int buf, int k0) {
        const uint32_t tA = tiles_u + (uint32_t)buf * 32768u;
        const uint32_t tB = tA + 16384u;
#pragma unroll
        for (int h = 0; h < 4; h++) {
            int r = lr + h * 32;
            uint32_t sw = SW128((uint32_t)(r * 128 + lc * 16));
            cp_async16(tA + sw, A  + (size_t)(bm + r) * K + k0 + lc * 8);
            cp_async16(tB + sw, Bw + (size_t)(bn + r) * K + k0 + lc * 8);
        }
        asm volatile("cp.async.commit_group;" ::: "memory");
    };

    const int a_row  = wm * 64 + (lane & 15);
    const int a_colb = (lane >> 4) << 4;
    const int b_row0 = wn * 32 + (lane & 7) + ((lane >> 4) << 3);
    const int b_colb = ((lane >> 3) & 1) << 4;

    auto ld_frags = [&](uint32_t tA, uint32_t tB, int kk,
                        uint32_t a[4][4], uint32_t bf[2][4]) {
        const int kb = kk * 32;
#pragma unroll
        for (int mt = 0; mt < 4; ++mt)
            ldsm_x4(a[mt][0], a[mt][1], a[mt][2], a[mt][3],
                    tA + SW128((uint32_t)((a_row + mt * 16) * 128 + kb + a_colb)));
#pragma unroll
        for (int np = 0; np < 2; ++np)
            ldsm_x4(bf[np][0], bf[np][1], bf[np][2], bf[np][3],
                    tB + SW128((uint32_t)((b_row0 + np * 16) * 128 + kb + b_colb)));
    };

    load_stage(0, 0);

    uint32_t afr[2][4][4], bfr[2][2][4];

    for (int s = 0; s < nsteps; ++s) {
        if (s + 1 < nsteps) {
            load_stage((s + 1) & 1, (s + 1) << 6);
            asm volatile("cp.async.wait_group 1;" ::: "memory");
        } else {
            asm volatile("cp.async.wait_group 0;" ::: "memory");
        }
        __syncthreads();

        const uint32_t tA = tiles_u + (uint32_t)(s & 1) * 32768u;
        const uint32_t tB = tA + 16384u;

        ld_frags(tA, tB, 0, afr[0], bfr[0]);
#pragma unroll
        for (int kk = 0; kk < 4; ++kk) {
            const int cur = kk & 1;
            if (kk < 3) ld_frags(tA, tB, kk + 1, afr[cur ^ 1], bfr[cur ^ 1]);
#pragma unroll
            for (int mt = 0; mt < 4; ++mt)
#pragma unroll
                for (int nt = 0; nt < 4; ++nt)
                    mma_bf16(acc[mt][nt], afr[cur][mt],
                             bfr[cur][nt >> 1][(nt & 1) * 2],
                             bfr[cur][nt >> 1][(nt & 1) * 2 + 1]);
        }
        __syncthreads();
    }

    const int g = lane >> 2, tg = lane & 3;
#pragma unroll
    for (int mt = 0; mt < 4; ++mt) {
#pragma unroll
        for (int nt = 0; nt < 4; ++nt) {
            const int m0 = bm + wm * 64 + mt * 16 + g;
            const int n0 = bn + wn * 32 + nt * 8 + tg * 2;
            float v0 = acc[mt][nt][0], v1 = acc[mt][nt][1];
            float v2 = acc[mt][nt][2], v3 = acc[mt][nt][3];
            if (BIAS) {
                float bb0 = bias[n0], bb1 = bias[n0 + 1];
                v0 += bb0; v1 += bb1; v2 += bb0; v3 += bb1;
            }
            v0 *= scale; v1 *= scale; v2 *= scale; v3 *= scale;
            if (RELU) {
                v0 = fmaxf(v0, 0.f); v1 = fmaxf(v1, 0.f);
                v2 = fmaxf(v2, 0.f); v3 = fmaxf(v3, 0.f);
            }
            if (OUT_BF16) {
                __nv_bfloat16* C = (__nv_bfloat16*)Cout;
                *(__nv_bfloat162*)(C + (size_t)m0 * N + n0)       = __floats2bfloat162_rn(v0, v1);
                *(__nv_bfloat162*)(C + (size_t)(m0 + 8) * N + n0) = __floats2bfloat162_rn(v2, v3);
            } else {
                float* C = (float*)Cout;
                *(float2*)(C + (size_t)m0 * N + n0)       = make_float2(v0, v1);
                *(float2*)(C + (size_t)(m0 + 8) * N + n0) = make_float2(v2, v3);
            }
        }
    }
}

// ======================= conversion / transpose ==============================
__global__ void cvt_bf16_kernel(const float* __restrict__ in,
                                __nv_bfloat16* __restrict__ out, int n4)
{
    int i = blockIdx.x * blockDim.x + threadIdx.x;
    if (i < n4) {
        float4 v = *(const float4*)(in + i * 4);
        __nv_bfloat162* o = (__nv_bfloat162*)(out + i * 4);
        o[0] = __floats2bfloat162_rn(v.x, v.y);
        o[1] = __floats2bfloat162_rn(v.z, v.w);
    }
}

struct TransJob { const float* in; __nv_bfloat16* out; int R, C; };
struct TransJobs6 { TransJob j[6]; };

__global__ void transpose_all_kernel(TransJobs6 jobs)
{
    __shared__ float tile[32][33];
    const TransJob j = jobs.j[blockIdx.z];
    const int c0 = blockIdx.x * 32, r0 = blockIdx.y * 32;
    if (c0 >= j.C || r0 >= j.R) return;
    const int tx = threadIdx.x, ty = threadIdx.y;
#pragma unroll
    for (int i = ty; i < 32; i += 8)
        tile[i][tx] = j.in[(size_t)(r0 + i) * j.C + c0 + tx];
    __syncthreads();
#pragma unroll
    for (int i = ty; i < 32; i += 8)
        j.out[(size_t)(c0 + i) * j.R + r0 + tx] = __float2bfloat16(tile[tx][i]);
}

// ======================= normalize 16K rows ==================================
__global__ void normalize_cat_kernel(const float* __restrict__ x,
                                     __nv_bfloat16* __restrict__ mp,
                                     __nv_bfloat16* __restrict__ ip)
{
    __shared__ float red[128];
    const int row = blockIdx.x, tid = threadIdx.x;
    const float* p = x + (size_t)row * PROJ;
    __nv_bfloat16* q = (row < B_SZ) ? (mp + (size_t)row * PROJ)
                                    : (ip + (size_t)(row - B_SZ) * PROJ);
    float s = 0.f;
    for (int j = tid; j < PROJ; j += 128) { float v = p[j]; s += v * v; }
    red[tid] = s; __syncthreads();
    for (int off = 64; off > 0; off >>= 1) {
        if (tid < off) red[tid] += red[tid + off];
        __syncthreads();
    }
    const float r = rsqrtf(red[0]);
    for (int j = tid; j < PROJ; j += 128) q[j] = __float2bfloat16(p[j] * r);
}

// ======================= mining + weighted CE (v8: shfl scans) ================
__device__ __forceinline__ unsigned mono(float f)
{
    unsigned u = __float_as_uint(f);
    return (u & 0x80000000u) ? ~u : (u | 0x80000000u);
}

// inclusive suffix sum over 256 threads; ONE __syncthreads; does not touch part[]
__device__ __forceinline__ unsigned suffix256(unsigned v, int lane, int w8,
                                              volatile unsigned* wtot)
{
#pragma unroll
    for (int off = 1; off < 32; off <<= 1) {
        unsigned t = __shfl_down_sync(0xFFFFFFFFu, v, off);
        if (lane + off < 32) v += t;
    }
    unsigned wt = __shfl_sync(0xFFFFFFFFu, v, 0);
    if (lane == 0) wtot[w8] = wt;
    __syncthreads();
    unsigned hi = 0;
#pragma unroll
    for (int w = 0; w < 8; ++w)
        if (w > w8) hi += wtot[w];
    return v + hi;
}

__global__ __launch_bounds__(256)
void mine_loss_kernel(const float* __restrict__ sim, const float* __restrict__ mw,
                      float* __restrict__ ce_out)
{
    __shared__ float    sh[B_SZ];
    __shared__ unsigned hist[2048];
    __shared__ unsigned part[256];
    __shared__ unsigned wtot[8];
    __shared__ float    wm8[8], ws8[8];
    __shared__ unsigned s_prefix;
    __shared__ int      s_kth;
    __shared__ int      s_cnt;
    __shared__ float    s_vdiag;

    const int bid   = blockIdx.x;
    const int modal = bid >> 13;
    const int row   = bid & (B_SZ - 1);
    const int tid   = threadIdx.x;
    const int lane  = tid & 31;
    const int w8    = tid >> 5;

    // zero histogram BEFORE the load sweep so load+hist can fuse
    for (int i = tid; i < 2048; i += 256) hist[i] = 0;
    __syncthreads();

    // fused: gmem row load -> smem + pass-1 histogram from registers
    const float4* srow4 = (const float4*)(sim + ((size_t)modal * B_SZ + row) * B_SZ);
    for (int j4 = tid; j4 < B_SZ / 4; j4 += 256) {
        const float4 v4 = srow4[j4];
        *(float4*)&sh[j4 * 4] = v4;
        const float vs[4] = { v4.x, v4.y, v4.z, v4.w };
#pragma unroll
        for (int k = 0; k < 4; ++k) {
            const int j = j4 * 4 + k;
            unsigned u = (j == row || vs[k] > 9.0f) ? 0u : mono(vs[k]);
            unsigned bin = u >> 21;
            unsigned peers = __match_any_sync(0xFFFFFFFFu, bin);
            if (lane == (unsigned)(__ffs(peers) - 1))
                atomicAdd(&hist[bin], (unsigned)__popc(peers));
        }
    }
    __syncthreads();

    // pass-1 select over 2048 bins (8 per thread), shfl suffix scan
    {
        unsigned loc[8];
        unsigned tot = 0;
#pragma unroll
        for (int i = 7; i >= 0; --i) { tot += hist[tid * 8 + i]; loc[i] = tot; }
        const unsigned suf = suffix256(tot, lane, w8, wtot);
        const unsigned above = suf - tot;
        if (above < KSEL && loc[0] + above >= KSEL) {
            int bi = 0;
#pragma unroll
            for (int i = 7; i >= 1; --i)
                if (loc[i] + above >= KSEL) { bi = i; break; }
            const unsigned nb = (bi < 7) ? loc[bi + 1] : 0u;
            s_prefix = (unsigned)(tid * 8 + bi) << 21;
            s_kth    = KSEL - (int)(nb + above);
        }
        if (tid == 0) s_cnt = 0;
    }
    __syncthreads();
    unsigned prefix = s_prefix;
    int kth = s_kth;
    const unsigned b1 = prefix >> 21;

    // compact boundary-bin candidates into hist[]
    for (int j = tid; j < B_SZ; j += 256) {
        float s = sh[j];
        unsigned u = (j == row || s > 9.0f) ? 0u : mono(s);
        if ((u >> 21) == b1) {
            int idx = atomicAdd(&s_cnt, 1);
            if (idx < 2048) hist[idx] = u;
        }
    }
    __syncthreads();
    const int cnt = s_cnt;

    unsigned thr;
    if (cnt <= 2048) {
        unsigned pre2 = prefix, pm2 = 0xFFE00000u;
        int k2 = kth;
        const int      sft[3] = {13, 5, 0};
        const unsigned msk[3] = {0xFFu, 0xFFu, 0x1Fu};
#pragma unroll
        for (int p = 0; p < 3; ++p) {
            part[tid] = 0;
            __syncthreads();
            for (int c = tid; c < cnt; c += 256) {
                unsigned u = hist[c];
                if ((u & pm2) == pre2)
                    atomicAdd(&part[(u >> sft[p]) & msk[p]], 1u);
            }
            __syncthreads();
            const unsigned mycnt = part[tid];
            const unsigned suf = suffix256(mycnt, lane, w8, wtot);   // 1 barrier
            if (suf >= (unsigned)k2 && (suf - mycnt) < (unsigned)k2) {
                s_prefix = pre2 | ((unsigned)tid << sft[p]);
                s_kth    = k2 - (int)(suf - mycnt);
            }
            __syncthreads();
            pre2 = s_prefix; k2 = s_kth;
            pm2 |= msk[p] << sft[p];
        }
        thr = pre2;
    } else {
        // fallback: full passes over bits [10,21) and [0,10)
        unsigned pm2 = 0xFFE00000u;
        const int      sft[2] = {10, 0};
        const unsigned msk[2] = {0x7FFu, 0x3FFu};
        for (int p = 0; p < 2; ++p) {
            for (int i = tid; i < 2048; i += 256) hist[i] = 0;
            __syncthreads();
            for (int j = tid; j < B_SZ; j += 256) {
                float s = sh[j];
                unsigned u = (j == row || s > 9.0f) ? 0u : mono(s);
                unsigned bin = ((u & pm2) == prefix) ? ((u >> sft[p]) & msk[p]) : 0xFFFFFFFFu;
                unsigned peers = __match_any_sync(0xFFFFFFFFu, bin);
                if (bin != 0xFFFFFFFFu && lane == (unsigned)(__ffs(peers) - 1))
                    atomicAdd(&hist[bin], (unsigned)__popc(peers));
            }
            __syncthreads();
            unsigned loc[8];
            unsigned tot = 0;
#pragma unroll
            for (int i = 7; i >= 0; --i) { tot += hist[tid * 8 + i]; loc[i] = tot; }
            const unsigned suf = suffix256(tot, lane, w8, wtot);
            const unsigned above = suf - tot;
            if (above < (unsigned)kth && loc[0] + above >= (unsigned)kth) {
                int bi = 0;
#pragma unroll
                for (int i = 7; i >= 1; --i)
                    if (loc[i] + above >= (unsigned)kth) { bi = i; break; }
                const unsigned nb = (bi < 7) ? loc[bi + 1] : 0u;
                s_prefix = prefix | ((unsigned)(tid * 8 + bi) << sft[p]);
                s_kth    = kth - (int)(nb + above);
            }
            __syncthreads();
            prefix = s_prefix; kth = s_kth;
            pm2 |= msk[p] << sft[p];
        }
        thr = prefix;
    }

    // fused weight + online softmax; shfl reduction
    float m = -3.402823466e38f, S = 0.f;
    for (int j = tid; j < B_SZ; j += 256) {
        float s = sh[j];
        bool diag  = (j == row);
        bool noise = (!diag) && (s > 9.0f);
        float w;
        if (noise)                        w = 0.5f;
        else if (!diag && mono(s) >= thr) w = 1.5f;
        else                              w = 1.0f;
        float v = s * w;
        if (diag) s_vdiag = v;
        if (v > m) { S = S * __expf(m - v) + 1.f; m = v; }
        else       { S += __expf(v - m); }
    }
#pragma unroll
    for (int off = 16; off > 0; off >>= 1) {
        float m2 = __shfl_down_sync(0xFFFFFFFFu, m, off);
        float S2 = __shfl_down_sync(0xFFFFFFFFu, S, off);
        if (lane + off < 32) {
            float M = fmaxf(m, m2);
            S = S * __expf(m - M) + S2 * __expf(m2 - M);
            m = M;
        }
    }
    if (lane == 0) { wm8[w8] = m; ws8[w8] = S; }
    __syncthreads();
    if (tid == 0) {
        float M = wm8[0], SS = ws8[0];
#pragma unroll
        for (int w = 1; w < 8; ++w) {
            float m2 = wm8[w], S2 = ws8[w];
            float Mn = fmaxf(M, m2);
            SS = SS * __expf(M - Mn) + S2 * __expf(m2 - Mn);
            M = Mn;
        }
        float lse = M + __logf(SS);
        float ce  = lse - s_vdiag;
        ce_out[modal * B_SZ + row] = ce * mw[(size_t)row * 2 + modal];
    }
}

__global__ void finalize_kernel(const float* __restrict__ ce, float* __restrict__ out)
{
    __shared__ float red[256];
    const int tid = threadIdx.x;
    float s = 0.f;
    for (int j = tid; j < 2 * B_SZ; j += 256) s += ce[j];
    red[tid] = s; __syncthreads();
    for (int off = 128; off > 0; off >>= 1) {
        if (tid < off) red[tid] += red[tid + off];
        __syncthreads();
    }
    if (tid == 0) out[0] = red[0] * (0.5f / (float)B_SZ);
}

// ======================= launch ==============================================
extern "C" void kernel_launch(void* const* d_in, const int* in_sizes, int n_in,
                              void* d_out, int out_size)
{
    const float* id_emb = (const float*)d_in[0];
    const float* text   = (const float*)d_in[1];
    const float* vis    = (const float*)d_in[2];
    const float* mw     = (const float*)d_in[3];
    const float* Wa_t = (const float*)d_in[4];  const float* ba_t = (const float*)d_in[5];
    const float* Wa_v = (const float*)d_in[6];  const float* ba_v = (const float*)d_in[7];
    const float* W1_t = (const float*)d_in[8];  const float* b1_t = (const float*)d_in[9];
    const float* W2_t = (const float*)d_in[10]; const float* b2_t = (const float*)d_in[11];
    const float* W1_v = (const float*)d_in[12]; const float* b1_v = (const float*)d_in[13];
    const float* W2_v = (const float*)d_in[14]; const float* b2_v = (const float*)d_in[15];

    __nv_bfloat16 *wa_t, *wa_v, *w1_t, *w1_v, *w2_t, *w2_v;
    __nv_bfloat16 *in_bf, *cat, *hcat, *mproj, *iproj;
    float *pcat, *sim, *ce;
    cudaGetSymbolAddress((void**)&wa_t, g_Wa_t);   cudaGetSymbolAddress((void**)&wa_v, g_Wa_v);
    cudaGetSymbolAddress((void**)&w1_t, g_W1_t);   cudaGetSymbolAddress((void**)&w1_v, g_W1_v);
    cudaGetSymbolAddress((void**)&w2_t, g_W2_t);   cudaGetSymbolAddress((void**)&w2_v, g_W2_v);
    cudaGetSymbolAddress((void**)&in_bf, g_in_bf);
    cudaGetSymbolAddress((void**)&cat,  g_cat);    cudaGetSymbolAddress((void**)&hcat, g_hcat);
    cudaGetSymbolAddress((void**)&pcat, g_pcat);
    cudaGetSymbolAddress((void**)&mproj, g_mproj); cudaGetSymbolAddress((void**)&iproj, g_iproj);
    cudaGetSymbolAddress((void**)&sim, g_sim);     cudaGetSymbolAddress((void**)&ce, g_ce);

    cudaFuncSetAttribute((const void*)hmma_gemm<false, true, true, false>,
                         cudaFuncAttributeMaxDynamicSharedMemorySize, TC_DSMEM);
    cudaFuncSetAttribute((const void*)hmma_gemm<true, true, true, false>,
                         cudaFuncAttributeMaxDynamicSharedMemorySize, TC_DSMEM);
    cudaFuncSetAttribute((const void*)hmma_gemm<false, true, false, false>,
                         cudaFuncAttributeMaxDynamicSharedMemorySize, TC_DSMEM);
    cudaFuncSetAttribute((const void*)hmma_gemm<false, false, false, true>,
                         cudaFuncAttributeMaxDynamicSharedMemorySize, TC_DSMEM);

    {
        TransJobs6 jobs = {{
            { Wa_t, wa_t, 768,  HID  },
            { Wa_v, wa_v, 2048, HID  },
            { W1_t, w1_t, HID,  HID  },
            { W1_v, w1_v, HID,  HID  },
            { W2_t, w2_t, HID,  PROJ },
            { W2_v, w2_v, HID,  PROJ },
        }};
        transpose_all_kernel<<<dim3(HID / 32, 2048 / 32, 6), dim3(32, 8)>>>(jobs);
    }
    cvt_bf16_kernel<<<(B_SZ * HID / 4 + 255) / 256, 256>>>(
        id_emb, cat + (size_t)B_SZ * HID, B_SZ * HID / 4);

    struct Modal {
        const float* f; int kf;
        const __nv_bfloat16 *wa, *w1, *w2;
        const float *ba, *b1, *b2;
    };
    const Modal ms[2] = {
        { text,  768, wa_t, w1_t, w2_t, ba_t, b1_t, b2_t },
        { vis,  2048, wa_v, w1_v, w2_v, ba_v, b1_v, b2_v },
    };

    for (int m = 0; m < 2; m++) {
        const int KF = ms[m].kf;
        cvt_bf16_kernel<<<(B_SZ * KF / 4 + 255) / 256, 256>>>(ms[m].f, in_bf, B_SZ * KF / 4);
        hmma_gemm<false, true, true, false><<<dim3(HID / 128, B_SZ / 128), 256, TC_DSMEM>>>(
            in_bf, ms[m].wa, ms[m].ba, cat, B_SZ, HID, KF, 1.f);
        hmma_gemm<true, true, true, false><<<dim3(HID / 128, 2 * B_SZ / 128), 256, TC_DSMEM>>>(
            cat, ms[m].w1, ms[m].b1, hcat, 2 * B_SZ, HID, HID, 1.f);
        hmma_gemm<false, true, false, false><<<dim3(PROJ / 128, 2 * B_SZ / 128), 256, TC_DSMEM>>>(
            hcat, ms[m].w2, ms[m].b2, pcat, 2 * B_SZ, PROJ, HID, 1.f);
        normalize_cat_kernel<<<2 * B_SZ, 128>>>(
            pcat, mproj + (size_t)m * B_SZ * PROJ, iproj + (size_t)m * B_SZ * PROJ);
    }

    hmma_gemm<false, false, false, true><<<dim3(B_SZ / 128, B_SZ / 128, 2), 256, TC_DSMEM>>>(
        iproj, mproj, nullptr, sim, B_SZ, B_SZ, PROJ, 10.0f);
    mine_loss_kernel<<<2 * B_SZ, 256>>>(sim, mw, ce);
    finalize_kernel<<<1, 256>>>(ce, (float*)d_out);
}